// round 10
// baseline (speedup 1.0000x reference)
#include <cuda_runtime.h>
#include <cuda_bf16.h>
#include <cstdint>

// y_t = d*y_{t-1} + x_t   per channel, y_{-1} = 0  (so y_0 = x_0)
// x: [BSZ=8, SEQ=4096, CH=1024] fp32, d: [CH] fp32, out same shape as x.
//
// R10: balance-optimal grid. One block per (batch, 8-channel group) column:
// 8 x 128 = 1024 blocks of 64 threads (NSUB=8 t-subtiles x 8 lanes).
// 1024 = 148*6 + 136 -> max 7 blocks on an SM vs ideal 6.92 = 98.9% balance
// (the 256-block shape capped at 86.5%). Each warp's row access is an
// aligned 32B sector (8 lanes x 4B) -> sector-granular, no DRAM overfetch.
//
// Same scan machinery as the best kernel (R5): 32 chunks of 128 steps;
// per chunk a register-local serial scan (TSUB=16), ONE bar.sync
// (subAgg parity-double-buffered), then every warp redundantly combines the
// 8 subtile aggregates (multiplier d^16) keeping a replicated carry.

#define BSZ    8
#define SEQ    4096
#define CH     1024
#define TSUB   16
#define NSUB   8
#define LANES  8                     // channels per block
#define NTHR   (NSUB * LANES)        // 64
#define CHUNK  (TSUB * NSUB)         // 128
#define NCHUNK (SEQ / CHUNK)         // 32
#define CGRPS  (CH / LANES)          // 128 channel groups per batch

__global__ __launch_bounds__(NTHR, 7)
void cummulsum_kernel(const float* __restrict__ x,
                      const float* __restrict__ d,
                      float* __restrict__ y)
{
    __shared__ float subAgg[2][NSUB][LANES];   // double-buffered by parity

    const int tid  = threadIdx.x;
    const int l8   = tid & (LANES - 1);  // lane within channel group 0..7
    const int s    = tid >> 3;           // subtile index 0..7
    const int b    = blockIdx.x >> 7;    // batch 0..7
    const int cg   = blockIdx.x & 127;   // channel group 0..127
    const int c    = cg * LANES + l8;    // channel

    const float dc = __ldg(d + c);
    // dT = dc^TSUB = dc^16
    float dT = dc * dc;  dT = dT * dT;  dT = dT * dT;  dT = dT * dT;

    const size_t colBase = ((size_t)b * SEQ) * CH + (size_t)c;
    const float* xp = x + colBase + (size_t)(s * TSUB) * CH;
    float*       yp = y + colBase + (size_t)(s * TSUB) * CH;

    float carry = 0.0f;   // replicated running state (identical in all warps)

    float xa[TSUB];
    float xb[TSUB];

    // Prologue: load chunk 0
    #pragma unroll
    for (int i = 0; i < TSUB; i++) xa[i] = xp[(size_t)i * CH];

    #pragma unroll 2
    for (int k = 0; k < NCHUNK; k++) {
        const int p = k & 1;

        // Prefetch next chunk; independent of everything below.
        const float* xpn = xp + (size_t)CHUNK * CH;
        if (k + 1 < NCHUNK) {
            #pragma unroll
            for (int i = 0; i < TSUB; i++) xb[i] = xpn[(size_t)i * CH];
        }

        // Local serial scan in place (zero initial condition)
        #pragma unroll
        for (int i = 1; i < TSUB; i++) xa[i] = fmaf(dc, xa[i - 1], xa[i]);

        subAgg[p][s][l8] = xa[TSUB - 1];
        __syncthreads();

        // Every warp redundantly combines the 8 subtile aggregates; uses the
        // prefix for its own subtile and updates its replicated carry.
        float P;                         // state entering subtile s
        {
            float r = carry;
            P = r;                       // valid if s == 0
            #pragma unroll
            for (int j = 0; j < NSUB; j++) {
                const float aggj = subAgg[p][j][l8];
                r = fmaf(dT, r, aggj);   // state entering subtile j+1
                if (j + 1 == s) P = r;
            }
            carry = r;                   // state entering next chunk
        }

        // Correction + store: y_i = ylocal_i + dc^(i+1) * P
        float f = dc;
        #pragma unroll
        for (int i = 0; i < TSUB; i++) {
            yp[(size_t)i * CH] = fmaf(f, P, xa[i]);
            f *= dc;
        }

        // Rotate buffers (dead on the final iteration; guarded)
        if (k + 1 < NCHUNK) {
            #pragma unroll
            for (int i = 0; i < TSUB; i++) xa[i] = xb[i];
        }

        xp += (size_t)CHUNK * CH;
        yp += (size_t)CHUNK * CH;
    }
}

extern "C" void kernel_launch(void* const* d_in, const int* in_sizes, int n_in,
                              void* d_out, int out_size)
{
    const float* x = (const float*)d_in[0];
    const float* d = (const float*)d_in[1];
    float*       y = (float*)d_out;
    (void)in_sizes; (void)n_in; (void)out_size;

    cummulsum_kernel<<<BSZ * CGRPS, NTHR>>>(x, d, y);
}

// round 11
// speedup vs baseline: 1.0345x; 1.0345x over previous
#include <cuda_runtime.h>
#include <cuda_bf16.h>
#include <cstdint>

// y_t = d*y_{t-1} + x_t   per channel, y_{-1} = 0  (so y_0 = x_0)
// x: [BSZ=8, SEQ=4096, CH=1024] fp32, d: [CH] fp32, out same shape as x.
//
// R11 = R5 (best known: one block per (batch, 32-ch group) column, 256 thr =
// 8 subtiles x 32 lanes, TSUB=16, ONE bar.sync per chunk, every warp
// redundantly combines the 8 subtile aggregates with multiplier d^16 and a
// replicated carry, pw[] power table on the store path)
// + PREFETCH DISTANCE 2 (triple register buffer): chunk k+2's loads issue at
// the top of chunk k, so ~32 LDGs/thread stay outstanding through the whole
// chunk body. Chip-wide in-flight load bytes ~8.4 MB (> 2x the ~3.8 MB DRAM
// saturation threshold) with 100% duty cycle — attacks the measured ~60%
// DRAM ceiling. Regs ~96 -> still 2 blocks/SM.

#define BSZ    8
#define SEQ    4096
#define CH     1024
#define TSUB   16
#define NSUB   8
#define NTHR   (NSUB * 32)          // 256
#define CHUNK  (TSUB * NSUB)        // 128
#define NCHUNK (SEQ / CHUNK)        // 32
#define CGRPS  (CH / 32)            // 32 channel groups per batch

__global__ __launch_bounds__(NTHR, 2)
void cummulsum_kernel(const float* __restrict__ x,
                      const float* __restrict__ d,
                      float* __restrict__ y)
{
    __shared__ float subAgg[2][NSUB][32];   // double-buffered by chunk parity

    const int tid  = threadIdx.x;
    const int lane = tid & 31;
    const int s    = tid >> 5;          // subtile index 0..7
    const int b    = blockIdx.x >> 5;   // batch 0..7
    const int cg   = blockIdx.x & 31;   // channel group 0..31
    const int c    = cg * 32 + lane;    // channel

    const float dc = __ldg(d + c);

    // Power table pw[i] = dc^(i+1); indexed in unrolled loops (keeps the
    // store path free of a serial multiply chain).
    float pw[TSUB];
    pw[0] = dc;
    #pragma unroll
    for (int i = 1; i < TSUB; i++) pw[i] = pw[i - 1] * dc;
    const float dT = pw[TSUB - 1];      // dc^16

    const size_t colBase = ((size_t)b * SEQ) * CH + (size_t)c;
    const float* xp = x + colBase + (size_t)(s * TSUB) * CH;
    float*       yp = y + colBase + (size_t)(s * TSUB) * CH;

    float carry = 0.0f;   // replicated per-warp running state (identical in all warps)

    float xa[TSUB];       // chunk k (being processed)
    float xb[TSUB];       // chunk k+1 (arrived / in flight)
    float xc[TSUB];       // chunk k+2 (in flight)

    // Prologue: issue loads for chunks 0 and 1.
    #pragma unroll
    for (int i = 0; i < TSUB; i++) xa[i] = xp[(size_t)i * CH];
    {
        const float* xp1 = xp + (size_t)CHUNK * CH;
        #pragma unroll
        for (int i = 0; i < TSUB; i++) xb[i] = xp1[(size_t)i * CH];
    }

    #pragma unroll 2
    for (int k = 0; k < NCHUNK; k++) {
        const int p = k & 1;

        // Prefetch chunk k+2: gets ~two full chunk bodies to complete, and
        // keeps loads in flight during combine + store of this chunk.
        const float* xpn = xp + (size_t)(2 * CHUNK) * CH;
        if (k + 2 < NCHUNK) {
            #pragma unroll
            for (int i = 0; i < TSUB; i++) xc[i] = xpn[(size_t)i * CH];
        }

        // Local serial scan in place (zero initial condition)
        #pragma unroll
        for (int i = 1; i < TSUB; i++) xa[i] = fmaf(dc, xa[i - 1], xa[i]);

        subAgg[p][s][lane] = xa[TSUB - 1];
        __syncthreads();

        // Every warp redundantly combines the 8 subtile aggregates; uses the
        // prefix for its own subtile and updates its replicated carry.
        float P;                         // state entering subtile s
        {
            float r = carry;
            P = r;                       // valid if s == 0
            #pragma unroll
            for (int j = 0; j < NSUB; j++) {
                const float aggj = subAgg[p][j][lane];
                r = fmaf(dT, r, aggj);   // state entering subtile j+1
                if (j + 1 == s) P = r;
            }
            carry = r;                   // state entering next chunk
        }

        // Correction + store: y_i = ylocal_i + dc^(i+1) * P
        #pragma unroll
        for (int i = 0; i < TSUB; i++) {
            yp[(size_t)i * CH] = fmaf(pw[i], P, xa[i]);
        }

        // Rotate buffers.
        #pragma unroll
        for (int i = 0; i < TSUB; i++) { xa[i] = xb[i]; xb[i] = xc[i]; }

        xp += (size_t)CHUNK * CH;
        yp += (size_t)CHUNK * CH;
    }
}

extern "C" void kernel_launch(void* const* d_in, const int* in_sizes, int n_in,
                              void* d_out, int out_size)
{
    const float* x = (const float*)d_in[0];
    const float* d = (const float*)d_in[1];
    float*       y = (float*)d_out;
    (void)in_sizes; (void)n_in; (void)out_size;

    cummulsum_kernel<<<BSZ * CGRPS, NTHR>>>(x, d, y);
}

// round 12
// speedup vs baseline: 1.1066x; 1.0697x over previous
#include <cuda_runtime.h>
#include <cuda_bf16.h>
#include <cstdint>

// y_t = d*y_{t-1} + x_t   per channel, y_{-1} = 0  (so y_0 = x_0)
// x: [BSZ=8, SEQ=4096, CH=1024] fp32, d: [CH] fp32, out same shape as x.
//
// R12: float2 lanes. Each lane owns 2 adjacent channels, so a warp's row
// access is 256B CONTIGUOUS (one LDG.64/lane) instead of an isolated 128B
// line per 4KB stride — halves the number of discrete DRAM extents chip-wide
// (attacks the measured ~60% DRAM ceiling, which survived every SM-side
// knob: warps/SM, prefetch depth, barrier count, cache policy).
//
// Block = 256 thr = NSUB(8) t-subtiles x 32 lanes -> 64-channel groups,
// grid = 8 batches x 16 groups = 128 blocks (single wave, 1 block/SM).
// Proven R5 machinery otherwise: TSUB=16, distance-1 prefetch, ONE bar.sync
// per chunk (subAgg parity-double-buffered), every warp redundantly combines
// the 8 subtile aggregates (multiplier d^16 per component) with a
// replicated carry.

#define BSZ    8
#define SEQ    4096
#define CH     1024
#define TSUB   16
#define NSUB   8
#define NTHR   (NSUB * 32)          // 256
#define CHUNK  (TSUB * NSUB)        // 128
#define NCHUNK (SEQ / CHUNK)        // 32
#define LANE_CH 2                   // channels per lane (float2)
#define GRP_CH (32 * LANE_CH)       // 64 channels per block
#define CGRPS  (CH / GRP_CH)        // 16 channel groups per batch

__global__ __launch_bounds__(NTHR, 2)
void cummulsum_kernel(const float* __restrict__ x,
                      const float* __restrict__ d,
                      float* __restrict__ y)
{
    __shared__ float2 subAgg[2][NSUB][32];   // double-buffered by chunk parity

    const int tid  = threadIdx.x;
    const int lane = tid & 31;
    const int s    = tid >> 5;            // subtile index 0..7
    const int b    = blockIdx.x >> 4;     // batch 0..7
    const int cg   = blockIdx.x & 15;     // channel group 0..15
    const int c0   = cg * GRP_CH + lane * LANE_CH;   // first channel of pair

    const float2 dc = *reinterpret_cast<const float2*>(d + c0);
    // dT = dc^TSUB = dc^16 (per component)
    float2 dT;
    dT.x = dc.x * dc.x; dT.x *= dT.x; dT.x *= dT.x; dT.x *= dT.x;
    dT.y = dc.y * dc.y; dT.y *= dT.y; dT.y *= dT.y; dT.y *= dT.y;

    const size_t colBase = ((size_t)b * SEQ) * CH + (size_t)c0;
    const float* xp = x + colBase + (size_t)(s * TSUB) * CH;
    float*       yp = y + colBase + (size_t)(s * TSUB) * CH;

    float2 carry = make_float2(0.0f, 0.0f);  // replicated running state

    float2 xa[TSUB];
    float2 xb[TSUB];

    // Prologue: load chunk 0 (LDG.64, 256B contiguous per warp-row)
    #pragma unroll
    for (int i = 0; i < TSUB; i++)
        xa[i] = *reinterpret_cast<const float2*>(xp + (size_t)i * CH);

    #pragma unroll 2
    for (int k = 0; k < NCHUNK; k++) {
        const int p = k & 1;

        // Prefetch next chunk; independent of everything below.
        const float* xpn = xp + (size_t)CHUNK * CH;
        if (k + 1 < NCHUNK) {
            #pragma unroll
            for (int i = 0; i < TSUB; i++)
                xb[i] = *reinterpret_cast<const float2*>(xpn + (size_t)i * CH);
        }

        // Local serial scan in place (zero initial condition), per component.
        #pragma unroll
        for (int i = 1; i < TSUB; i++) {
            xa[i].x = fmaf(dc.x, xa[i - 1].x, xa[i].x);
            xa[i].y = fmaf(dc.y, xa[i - 1].y, xa[i].y);
        }

        subAgg[p][s][lane] = xa[TSUB - 1];
        __syncthreads();

        // Every warp redundantly combines the 8 subtile aggregates; uses the
        // prefix for its own subtile and updates its replicated carry.
        float2 P;                        // state entering subtile s
        {
            float2 r = carry;
            P = r;                       // valid if s == 0
            #pragma unroll
            for (int j = 0; j < NSUB; j++) {
                const float2 aggj = subAgg[p][j][lane];
                r.x = fmaf(dT.x, r.x, aggj.x);   // state entering subtile j+1
                r.y = fmaf(dT.y, r.y, aggj.y);
                if (j + 1 == s) P = r;
            }
            carry = r;                   // state entering next chunk
        }

        // Correction + store: y_i = ylocal_i + dc^(i+1) * P  (STG.64)
        float2 f = dc;
        #pragma unroll
        for (int i = 0; i < TSUB; i++) {
            float2 o;
            o.x = fmaf(f.x, P.x, xa[i].x);
            o.y = fmaf(f.y, P.y, xa[i].y);
            *reinterpret_cast<float2*>(yp + (size_t)i * CH) = o;
            f.x *= dc.x;
            f.y *= dc.y;
        }

        // Rotate buffers (dead on the final iteration; guarded)
        if (k + 1 < NCHUNK) {
            #pragma unroll
            for (int i = 0; i < TSUB; i++) xa[i] = xb[i];
        }

        xp += (size_t)CHUNK * CH;
        yp += (size_t)CHUNK * CH;
    }
}

extern "C" void kernel_launch(void* const* d_in, const int* in_sizes, int n_in,
                              void* d_out, int out_size)
{
    const float* x = (const float*)d_in[0];
    const float* d = (const float*)d_in[1];
    float*       y = (float*)d_out;
    (void)in_sizes; (void)n_in; (void)out_size;

    cummulsum_kernel<<<BSZ * CGRPS, NTHR>>>(x, d, y);
}

// round 14
// speedup vs baseline: 1.1963x; 1.0810x over previous
#include <cuda_runtime.h>
#include <cuda_bf16.h>
#include <cstdint>

// y_t = d*y_{t-1} + x_t   per channel, y_{-1} = 0  (so y_0 = x_0)
// x: [BSZ=8, SEQ=4096, CH=1024] fp32, d: [CH] fp32, out same shape as x.
//
// FINAL (== R5, measured best: 45.2us kernel / 51.4us wall, DRAM ~60%).
// One block per (batch, 32-channel group) column = 256 blocks,
// 256 threads = NSUB(8) t-subtiles x 32 channels, 2 blocks/SM (80 regs).
// 32 chunks of 128 timesteps; per chunk: register-local serial scan,
// one bar.sync (subAgg parity-double-buffered), then EVERY warp redundantly
// combines the 8 subtile aggregates (multiplier d^16) keeping a replicated
// carry register -> no warp-0 critical section, no second barrier.
//
// Roofline note: the kernel is a fully-interleaved 50/50 read/write stream
// (268 MB total). At mixed-stream HBM efficiency (~75% of peak) the floor is
// ~45us, which this kernel hits; deeper prefetch, cache hints, wider/narrower
// extents, more/fewer warps, and t-chaining all measured neutral-to-worse
// (R4, R6, R8, R9, R10, R11, R12).

#define BSZ    8
#define SEQ    4096
#define CH     1024
#define TSUB   16
#define NSUB   8
#define NTHR   (NSUB * 32)          // 256
#define CHUNK  (TSUB * NSUB)        // 128
#define NCHUNK (SEQ / CHUNK)        // 32
#define CGRPS  (CH / 32)            // 32 channel groups per batch

__global__ __launch_bounds__(NTHR, 2)
void cummulsum_kernel(const float* __restrict__ x,
                      const float* __restrict__ d,
                      float* __restrict__ y)
{
    __shared__ float subAgg[2][NSUB][32];   // double-buffered by chunk parity

    const int tid  = threadIdx.x;
    const int lane = tid & 31;
    const int s    = tid >> 5;          // subtile index 0..7
    const int b    = blockIdx.x >> 5;   // batch 0..7
    const int cg   = blockIdx.x & 31;   // channel group 0..31
    const int c    = cg * 32 + lane;    // channel

    const float dc = __ldg(d + c);

    // Power table pw[i] = dc^(i+1); indexed in unrolled loops (no serial
    // multiply chain on the store path).
    float pw[TSUB];
    pw[0] = dc;
    #pragma unroll
    for (int i = 1; i < TSUB; i++) pw[i] = pw[i - 1] * dc;
    const float dT = pw[TSUB - 1];      // dc^16

    const size_t colBase = ((size_t)b * SEQ) * CH + (size_t)c;
    const float* xp = x + colBase + (size_t)(s * TSUB) * CH;
    float*       yp = y + colBase + (size_t)(s * TSUB) * CH;

    float carry = 0.0f;   // replicated per-warp running state (identical in all warps)

    float xa[TSUB];
    float xb[TSUB];

    // Prologue: load chunk 0
    #pragma unroll
    for (int i = 0; i < TSUB; i++) xa[i] = xp[(size_t)i * CH];

    #pragma unroll 2
    for (int k = 0; k < NCHUNK; k++) {
        const int p = k & 1;

        // Prefetch next chunk (independent of everything below).
        const float* xpn = xp + (size_t)CHUNK * CH;
        if (k + 1 < NCHUNK) {
            #pragma unroll
            for (int i = 0; i < TSUB; i++) xb[i] = xpn[(size_t)i * CH];
        }

        // Local serial scan in place (zero initial condition)
        #pragma unroll
        for (int i = 1; i < TSUB; i++) xa[i] = fmaf(dc, xa[i - 1], xa[i]);

        subAgg[p][s][lane] = xa[TSUB - 1];
        __syncthreads();

        // Every warp redundantly scans all 8 aggregates; it uses the prefix
        // for its own subtile and updates its private replicated carry.
        float P;                         // state entering subtile s
        {
            float agg[NSUB];
            #pragma unroll
            for (int j = 0; j < NSUB; j++) agg[j] = subAgg[p][j][lane];
            float r = carry;
            P = r;                       // valid if s == 0
            #pragma unroll
            for (int j = 0; j < NSUB; j++) {
                r = fmaf(dT, r, agg[j]); // state entering subtile j+1
                if (j + 1 == s) P = r;
            }
            carry = r;                   // state entering next chunk
        }

        // Correction + store: y_i = ylocal_i + dc^(i+1) * P
        #pragma unroll
        for (int i = 0; i < TSUB; i++) {
            yp[(size_t)i * CH] = fmaf(pw[i], P, xa[i]);
        }

        // Rotate buffers
        #pragma unroll
        for (int i = 0; i < TSUB; i++) xa[i] = xb[i];

        xp += (size_t)CHUNK * CH;
        yp += (size_t)CHUNK * CH;
    }
}

extern "C" void kernel_launch(void* const* d_in, const int* in_sizes, int n_in,
                              void* d_out, int out_size)
{
    const float* x = (const float*)d_in[0];
    const float* d = (const float*)d_in[1];
    float*       y = (float*)d_out;
    (void)in_sizes; (void)n_in; (void)out_size;

    cummulsum_kernel<<<BSZ * CGRPS, NTHR>>>(x, d, y);
}